// round 16
// baseline (speedup 1.0000x reference)
#include <cuda_runtime.h>
#include <cuda_bf16.h>
#include <cstdint>

#define HH 128
#define NPAD 100096          // = 782*128
#define EMAX 1600000
#define NTH 256
#define SCAN_B 512
// dynamic smem for fused combine: meanS 128*68*8 + As 2*128*9*8 + Ws 2*8*132*8
#define MEAN_BYTES 69632
#define AS_BYTES   18432
#define WS_BYTES   16896
#define DSM_TOTAL  (MEAN_BYTES + AS_BYTES + WS_BYTES)

// ---------------- scratch ----------------
__device__ float g_xp [NPAD * HH];
__device__ float g_h  [NPAD * HH];
__device__ float g_xp0[NPAD * 2];
__device__ int   g_deg [NPAD];
__device__ int   g_off [NPAD + 1];
__device__ int   g_cur [NPAD];
__device__ int   g_srcs[EMAX];
__device__ int   g_bsum [4096];
__device__ int   g_bsumx[4096];

__device__ __forceinline__ float warp_sum(float v) {
#pragma unroll
    for (int o = 16; o > 0; o >>= 1) v += __shfl_xor_sync(0xffffffffu, v, o);
    return v;
}
__device__ __forceinline__ float quad_sum(float v) {
    v += __shfl_xor_sync(0xffffffffu, v, 1);
    v += __shfl_xor_sync(0xffffffffu, v, 2);
    return v;
}
__device__ __forceinline__ uint32_t pack_hilo(float a, float b, uint32_t& lo) {
    __nv_bfloat16 ha = __float2bfloat16(a), hb = __float2bfloat16(b);
    float ra = a - __bfloat162float(ha), rb = b - __bfloat162float(hb);
    __nv_bfloat16 la = __float2bfloat16(ra), lb = __float2bfloat16(rb);
    lo = (uint32_t)__bfloat16_as_ushort(la) | ((uint32_t)__bfloat16_as_ushort(lb) << 16);
    return (uint32_t)__bfloat16_as_ushort(ha) | ((uint32_t)__bfloat16_as_ushort(hb) << 16);
}
__device__ __forceinline__ uint2 pack2(float a, float b) {
    uint2 e; uint32_t lo;
    e.x = pack_hilo(a, b, lo); e.y = lo;
    return e;
}

#define MMA_BF16(d, a, b0v, b1v)                                                 \
    asm volatile(                                                                \
        "mma.sync.aligned.m16n8k16.row.col.f32.bf16.bf16.f32 "                   \
        "{%0,%1,%2,%3}, {%4,%5,%6,%7}, {%8,%9}, {%0,%1,%2,%3};"                  \
        : "+f"(d[0]), "+f"(d[1]), "+f"(d[2]), "+f"(d[3])                         \
        : "r"((a)[0]), "r"((a)[1]), "r"((a)[2]), "r"((a)[3]), "r"(b0v), "r"(b1v))

// ================= hist + layer-0 projection, fused =================
__global__ void k_hist_l0(const int* __restrict__ ei, int E,
                          const float* __restrict__ x, const float* __restrict__ Wp,
                          const float* __restrict__ bp, int n) {
    int e = blockIdx.x * blockDim.x + threadIdx.x;
    if (e < n) {
        float x0 = x[2 * e], x1 = x[2 * e + 1];
        g_xp0[2 * e]     = fmaxf(fmaf(x0, Wp[0], fmaf(x1, Wp[2], bp[0])), 0.f);
        g_xp0[2 * e + 1] = fmaxf(fmaf(x0, Wp[1], fmaf(x1, Wp[3], bp[1])), 0.f);
    }
    if (e < E) atomicAdd(&g_deg[ei[E + e]], 1);
}

// ================= CSR scans =================
__global__ void __launch_bounds__(SCAN_B) k_scan1(int n) {
    __shared__ int sm[SCAN_B];
    int t = threadIdx.x;
    int idx = blockIdx.x * SCAN_B + t;
    int v = (idx < n) ? g_deg[idx] : 0;
    sm[t] = v;
    __syncthreads();
#pragma unroll
    for (int off = 1; off < SCAN_B; off <<= 1) {
        int add = (t >= off) ? sm[t - off] : 0;
        __syncthreads();
        sm[t] += add;
        __syncthreads();
    }
    if (idx < n) g_off[idx] = sm[t] - v;
    if (t == SCAN_B - 1) g_bsum[blockIdx.x] = sm[t];
}
__global__ void __launch_bounds__(1024) k_scan2(int nb) {
    __shared__ int sm[1024];
    int t = threadIdx.x;
    int v = (t < nb) ? g_bsum[t] : 0;
    sm[t] = v;
    __syncthreads();
#pragma unroll
    for (int off = 1; off < 1024; off <<= 1) {
        int add = (t >= off) ? sm[t - off] : 0;
        __syncthreads();
        sm[t] += add;
        __syncthreads();
    }
    if (t < nb) g_bsumx[t] = sm[t] - v;
}
__global__ void k_scan3(int n, int E) {
    int idx = blockIdx.x * blockDim.x + threadIdx.x;
    if (idx == 0) g_off[n] = E;
    if (idx >= n) return;
    int o = g_off[idx] + g_bsumx[idx / SCAN_B];
    g_off[idx] = o;
    g_cur[idx] = o;
}
__global__ void k_scatter(const int* __restrict__ ei, int E) {
    int e = blockIdx.x * blockDim.x + threadIdx.x;
    if (e >= E) return;
    int s = ei[e], d = ei[E + e];
    int pos = atomicAdd(&g_cur[d], 1);
    g_srcs[pos] = s;
}

// ============ layer 0 combine: CSR mean-gather (dim2) + combine + LN ============
__global__ void __launch_bounds__(256) k_combine0(int n, const float* __restrict__ Wl,
        const float* __restrict__ bl, const float* __restrict__ Wr,
        const float* __restrict__ lnw, const float* __restrict__ lnb) {
    int node = (blockIdx.x * 256 + threadIdx.x) >> 5;
    int lane = threadIdx.x & 31;
    if (node >= n) return;
    int beg = g_off[node], end = g_off[node + 1];
    float m0 = 0.f, m1 = 0.f;
    for (int j = beg + lane; j < end; j += 32) {
        int s = __ldg(&g_srcs[j]);
        float2 v = *(const float2*)&g_xp0[2 * s];
        m0 += v.x; m1 += v.y;
    }
    m0 = warp_sum(m0); m1 = warp_sum(m1);
    float inv = 1.f / fmaxf((float)(end - beg), 1.f);
    m0 *= inv; m1 *= inv;
    float p0 = g_xp0[2 * node], p1 = g_xp0[2 * node + 1];
    float v[4]; float s = 0.f;
#pragma unroll
    for (int k = 0; k < 4; k++) {
        int c = lane + 32 * k;
        v[k] = fmaf(m0, Wl[c], fmaf(m1, Wl[HH + c],
               fmaf(p0, Wr[c], fmaf(p1, Wr[HH + c], bl[c]))));
        s += v[k];
    }
    s = warp_sum(s);
    float mu = s * (1.f / HH);
    float q = 0.f;
#pragma unroll
    for (int k = 0; k < 4; k++) { v[k] -= mu; q += v[k] * v[k]; }
    q = warp_sum(q);
    float rstd = rsqrtf(q * (1.f / HH) + 1e-5f);
    size_t base = (size_t)node * HH;
#pragma unroll
    for (int k = 0; k < 4; k++) {
        int c = lane + 32 * k;
        g_h[base + c] = v[k] * rstd * lnw[c] + lnb[c];
    }
}

// =================== bf16x3 MMA GEMM core (r13) ===================
#define GEMM_DECLS                                                            \
    const int t = threadIdx.x;                                                \
    const int warp = t >> 5, lane = t & 31;                                   \
    const int g = lane >> 2, q = lane & 3;                                    \
    const int mrow = (warp & 3) * 32;                                         \
    const int n0 = (warp >> 2) * 64;                                          \
    const int nhalf = warp >> 2;                                              \
    const int ar = t >> 1, akb = (t & 1) * 8, ac4 = (t & 1) * 4;              \
    const int k2r = t >> 5, nb = (t & 31) * 4;                                \
    float4 pa0, pa1, pw0, pw1;                                                \
    float c[2][8][4];                                                         \
    _Pragma("unroll")                                                         \
    for (int mt = 0; mt < 2; mt++)                                            \
        _Pragma("unroll")                                                     \
        for (int j = 0; j < 8; j++)                                           \
            _Pragma("unroll")                                                 \
            for (int u = 0; u < 4; u++) c[mt][j][u] = 0.f;                    \
    (void)nhalf; (void)pa0; (void)pa1;

#define STAGE(buf)                                                            \
    {                                                                         \
        uint32_t lo_; uint2 e_;                                               \
        e_.x = pack_hilo(pa0.x, pa0.y, lo_); e_.y = lo_; As[buf][ar][ac4 + 0] = e_; \
        e_.x = pack_hilo(pa0.z, pa0.w, lo_); e_.y = lo_; As[buf][ar][ac4 + 1] = e_; \
        e_.x = pack_hilo(pa1.x, pa1.y, lo_); e_.y = lo_; As[buf][ar][ac4 + 2] = e_; \
        e_.x = pack_hilo(pa1.z, pa1.w, lo_); e_.y = lo_; As[buf][ar][ac4 + 3] = e_; \
        e_.x = pack_hilo(pw0.x, pw1.x, lo_); e_.y = lo_; Ws[buf][k2r][nb + 0] = e_; \
        e_.x = pack_hilo(pw0.y, pw1.y, lo_); e_.y = lo_; Ws[buf][k2r][nb + 1] = e_; \
        e_.x = pack_hilo(pw0.z, pw1.z, lo_); e_.y = lo_; Ws[buf][k2r][nb + 2] = e_; \
        e_.x = pack_hilo(pw0.w, pw1.w, lo_); e_.y = lo_; Ws[buf][k2r][nb + 3] = e_; \
    }

#define PREFETCH(Ap, Wp_)                                                     \
    {                                                                         \
        pa0 = *(const float4*)((Ap) + akb);                                   \
        pa1 = *(const float4*)((Ap) + akb + 4);                               \
        pw0 = *(const float4*)&(Wp_)[(size_t)(2 * k2r) * HH + nb];            \
        pw1 = *(const float4*)&(Wp_)[(size_t)(2 * k2r + 1) * HH + nb];        \
    }
#define PREFETCH_W(Wp_)                                                       \
    {                                                                         \
        pw0 = *(const float4*)&(Wp_)[(size_t)(2 * k2r) * HH + nb];            \
        pw1 = *(const float4*)&(Wp_)[(size_t)(2 * k2r + 1) * HH + nb];        \
    }
#define STAGE_W(buf)                                                          \
    {                                                                         \
        uint32_t lo_; uint2 e_;                                               \
        e_.x = pack_hilo(pw0.x, pw1.x, lo_); e_.y = lo_; Ws[buf][k2r][nb + 0] = e_; \
        e_.x = pack_hilo(pw0.y, pw1.y, lo_); e_.y = lo_; Ws[buf][k2r][nb + 1] = e_; \
        e_.x = pack_hilo(pw0.z, pw1.z, lo_); e_.y = lo_; Ws[buf][k2r][nb + 2] = e_; \
        e_.x = pack_hilo(pw0.w, pw1.w, lo_); e_.y = lo_; Ws[buf][k2r][nb + 3] = e_; \
    }

#define GEMM_COMPUTE(cur)                                                     \
    {                                                                         \
        uint32_t ah[2][4], al[2][4];                                          \
        _Pragma("unroll")                                                     \
        for (int mt = 0; mt < 2; mt++) {                                      \
            int r = mrow + mt * 16;                                           \
            uint2 x0 = As[cur][r + g][q];                                     \
            uint2 x1 = As[cur][r + g + 8][q];                                 \
            uint2 x2 = As[cur][r + g][q + 4];                                 \
            uint2 x3 = As[cur][r + g + 8][q + 4];                             \
            ah[mt][0] = x0.x; al[mt][0] = x0.y;                               \
            ah[mt][1] = x1.x; al[mt][1] = x1.y;                               \
            ah[mt][2] = x2.x; al[mt][2] = x2.y;                               \
            ah[mt][3] = x3.x; al[mt][3] = x3.y;                               \
        }                                                                     \
        _Pragma("unroll")                                                     \
        for (int j = 0; j < 8; j++) {                                         \
            int nn = n0 + 8 * j + g;                                          \
            uint2 b0 = Ws[cur][q][nn];                                        \
            uint2 b1 = Ws[cur][q + 4][nn];                                    \
            MMA_BF16(c[0][j], ah[0], b0.y, b1.y);                             \
            MMA_BF16(c[0][j], al[0], b0.x, b1.x);                             \
            MMA_BF16(c[0][j], ah[0], b0.x, b1.x);                             \
            MMA_BF16(c[1][j], ah[1], b0.y, b1.y);                             \
            MMA_BF16(c[1][j], al[1], b0.x, b1.x);                             \
            MMA_BF16(c[1][j], ah[1], b0.x, b1.x);                             \
        }                                                                     \
    }

// mean-stage compute: A fragments straight from meanS (pairs st*8+q / +q+4)
#define GEMM_COMPUTE_M(cur, st)                                               \
    {                                                                         \
        uint32_t ah[2][4], al[2][4];                                          \
        _Pragma("unroll")                                                     \
        for (int mt = 0; mt < 2; mt++) {                                      \
            int r = mrow + mt * 16;                                           \
            uint2 x0 = meanS[r + g][(st) * 8 + q];                            \
            uint2 x1 = meanS[r + g + 8][(st) * 8 + q];                        \
            uint2 x2 = meanS[r + g][(st) * 8 + q + 4];                        \
            uint2 x3 = meanS[r + g + 8][(st) * 8 + q + 4];                    \
            ah[mt][0] = x0.x; al[mt][0] = x0.y;                               \
            ah[mt][1] = x1.x; al[mt][1] = x1.y;                               \
            ah[mt][2] = x2.x; al[mt][2] = x2.y;                               \
            ah[mt][3] = x3.x; al[mt][3] = x3.y;                               \
        }                                                                     \
        _Pragma("unroll")                                                     \
        for (int j = 0; j < 8; j++) {                                         \
            int nn = n0 + 8 * j + g;                                          \
            uint2 b0 = Ws[cur][q][nn];                                        \
            uint2 b1 = Ws[cur][q + 4][nn];                                    \
            MMA_BF16(c[0][j], ah[0], b0.y, b1.y);                             \
            MMA_BF16(c[0][j], al[0], b0.x, b1.x);                             \
            MMA_BF16(c[0][j], ah[0], b0.x, b1.x);                             \
            MMA_BF16(c[1][j], ah[1], b0.y, b1.y);                             \
            MMA_BF16(c[1][j], al[1], b0.x, b1.x);                             \
            MMA_BF16(c[1][j], ah[1], b0.x, b1.x);                             \
        }                                                                     \
    }

#define GATHER_NODE(idx)                                                      \
    {                                                                         \
        int beg_ = sbeg[idx], end_ = send[idx];                               \
        float4 a0g = make_float4(0.f, 0.f, 0.f, 0.f);                         \
        float4 a1g = make_float4(0.f, 0.f, 0.f, 0.f);                         \
        int j_ = beg_;                                                        \
        for (; j_ + 2 <= end_; j_ += 2) {                                     \
            int s0_ = __ldg(&g_srcs[j_]), s1_ = __ldg(&g_srcs[j_ + 1]);       \
            float4 v0_ = *(const float4*)&g_xp[(size_t)s0_ * HH + lane * 4];  \
            float4 v1_ = *(const float4*)&g_xp[(size_t)s1_ * HH + lane * 4];  \
            a0g.x += v0_.x; a0g.y += v0_.y; a0g.z += v0_.z; a0g.w += v0_.w;   \
            a1g.x += v1_.x; a1g.y += v1_.y; a1g.z += v1_.z; a1g.w += v1_.w;   \
        }                                                                     \
        if (j_ < end_) {                                                      \
            int s0_ = __ldg(&g_srcs[j_]);                                     \
            float4 v0_ = *(const float4*)&g_xp[(size_t)s0_ * HH + lane * 4];  \
            a0g.x += v0_.x; a0g.y += v0_.y; a0g.z += v0_.z; a0g.w += v0_.w;   \
        }                                                                     \
        float invd_ = 1.f / fmaxf((float)(end_ - beg_), 1.f);                 \
        meanS[idx][lane * 2]     = pack2((a0g.x + a1g.x) * invd_,             \
                                         (a0g.y + a1g.y) * invd_);            \
        meanS[idx][lane * 2 + 1] = pack2((a0g.z + a1g.z) * invd_,             \
                                         (a0g.w + a1g.w) * invd_);            \
    }

// ---------------- proj GEMM: xp = relu(h @ Wp + bp), K=128 ----------------
__global__ void __launch_bounds__(NTH, 2) k_proj(const float* __restrict__ W,
                                                 const float* __restrict__ bias) {
    __shared__ uint2 As[2][128][9];
    __shared__ uint2 Ws[2][8][132];
    GEMM_DECLS
    const int row0 = blockIdx.x * 128;
    const float* Arow = &g_h[(size_t)(row0 + ar) * HH];

    PREFETCH(Arow, W);
    STAGE(0);
    const int NT = 8;
#pragma unroll 2
    for (int it = 0; it < NT; it++) {
        int cur = it & 1;
        __syncthreads();
        if (it + 1 < NT) {
            int k0 = (it + 1) * 16;
            PREFETCH(Arow + k0, W + (size_t)k0 * HH);
        }
        GEMM_COMPUTE(cur)
        if (it + 1 < NT) STAGE(cur ^ 1);
    }

#pragma unroll
    for (int mt = 0; mt < 2; mt++) {
        int r0 = row0 + mrow + mt * 16 + g, r1 = r0 + 8;
#pragma unroll
        for (int j = 0; j < 8; j++) {
            int jc = n0 + 8 * j + 2 * q;
            float2 bv = *(const float2*)&bias[jc];
            float2 o0, o1;
            o0.x = fmaxf(c[mt][j][0] + bv.x, 0.f); o0.y = fmaxf(c[mt][j][1] + bv.y, 0.f);
            o1.x = fmaxf(c[mt][j][2] + bv.x, 0.f); o1.y = fmaxf(c[mt][j][3] + bv.y, 0.f);
            *(float2*)&g_xp[(size_t)r0 * HH + jc] = o0;
            *(float2*)&g_xp[(size_t)r1 * HH + jc] = o1;
        }
    }
}

// ==== FUSED combine: per-block gather (hidden under xp@Wr stages) + mean@Wl + LN ====
__global__ void __launch_bounds__(NTH, 1) k_combine(int n, const float* __restrict__ Wl,
        const float* __restrict__ Wr, const float* __restrict__ bl,
        const float* __restrict__ lnw, const float* __restrict__ lnb) {
    extern __shared__ __align__(16) char dsm[];
    uint2 (*meanS)[68] = (uint2(*)[68])dsm;
    uint2 (*As)[128][9] = (uint2(*)[128][9])(dsm + MEAN_BYTES);
    uint2 (*Ws)[8][132] = (uint2(*)[8][132])(dsm + MEAN_BYTES + AS_BYTES);
    __shared__ float pbuf[128][2];
    __shared__ float vbuf[128][2];
    __shared__ int sbeg[128], send[128];
    GEMM_DECLS
    const int row0 = blockIdx.x * 128;
    const float* Ax = &g_xp[(size_t)(row0 + ar) * HH];

    if (t < 128) {
        int nd = row0 + t;
        if (nd < n) { sbeg[t] = g_off[nd]; send[t] = g_off[nd + 1]; }
        else        { sbeg[t] = 0; send[t] = 0; }
    }

    // ---- phase 1: xp @ Wr (stages 0..7), gather interleaved (2 nodes/warp/stage) ----
    PREFETCH(Ax, Wr);
    STAGE(0);
    __syncthreads();   // also covers sbeg/send
#pragma unroll 2
    for (int it = 0; it < 8; it++) {
        int cur = it & 1;
        if (it) __syncthreads();
        if (it + 1 < 8) {
            int k0 = (it + 1) * 16;
            PREFETCH(Ax + k0, Wr + (size_t)k0 * HH);
        }
        GEMM_COMPUTE(cur)
        GATHER_NODE(warp * 16 + it * 2)
        GATHER_NODE(warp * 16 + it * 2 + 1)
        if (it + 1 < 8) STAGE(cur ^ 1);
    }

    // ---- phase 2: mean @ Wl (stages 0..7), A direct from meanS ----
    PREFETCH_W(Wl);
    STAGE_W(0);
    __syncthreads();   // meanS + Ws[0] ready
#pragma unroll 2
    for (int it = 0; it < 8; it++) {
        int cur = it & 1;
        if (it) __syncthreads();
        if (it + 1 < 8) PREFETCH_W(Wl + (size_t)(it + 1) * 16 * HH);
        GEMM_COMPUTE_M(cur, it)
        if (it + 1 < 8) STAGE_W(cur ^ 1);
    }

    // ---- epilogue: bias + LN (r13) ----
    float s[2][2];
#pragma unroll
    for (int mt = 0; mt < 2; mt++) { s[mt][0] = 0.f; s[mt][1] = 0.f; }
#pragma unroll
    for (int mt = 0; mt < 2; mt++)
#pragma unroll
        for (int j = 0; j < 8; j++) {
            int jc = n0 + 8 * j + 2 * q;
            float2 bv = *(const float2*)&bl[jc];
            c[mt][j][0] += bv.x; c[mt][j][1] += bv.y;
            c[mt][j][2] += bv.x; c[mt][j][3] += bv.y;
            s[mt][0] += c[mt][j][0] + c[mt][j][1];
            s[mt][1] += c[mt][j][2] + c[mt][j][3];
        }
#pragma unroll
    for (int mt = 0; mt < 2; mt++) { s[mt][0] = quad_sum(s[mt][0]); s[mt][1] = quad_sum(s[mt][1]); }
    __syncthreads();
    if (q == 0) {
#pragma unroll
        for (int mt = 0; mt < 2; mt++) {
            pbuf[mrow + mt * 16 + g][nhalf] = s[mt][0];
            pbuf[mrow + mt * 16 + g + 8][nhalf] = s[mt][1];
        }
    }
    __syncthreads();
    float mu[2][2], vs[2][2];
#pragma unroll
    for (int mt = 0; mt < 2; mt++) {
        int lr0 = mrow + mt * 16 + g;
        mu[mt][0] = (pbuf[lr0][0] + pbuf[lr0][1]) * (1.f / HH);
        mu[mt][1] = (pbuf[lr0 + 8][0] + pbuf[lr0 + 8][1]) * (1.f / HH);
        vs[mt][0] = 0.f; vs[mt][1] = 0.f;
    }
#pragma unroll
    for (int mt = 0; mt < 2; mt++)
#pragma unroll
        for (int j = 0; j < 8; j++) {
            c[mt][j][0] -= mu[mt][0]; c[mt][j][1] -= mu[mt][0];
            c[mt][j][2] -= mu[mt][1]; c[mt][j][3] -= mu[mt][1];
            vs[mt][0] += c[mt][j][0] * c[mt][j][0] + c[mt][j][1] * c[mt][j][1];
            vs[mt][1] += c[mt][j][2] * c[mt][j][2] + c[mt][j][3] * c[mt][j][3];
        }
#pragma unroll
    for (int mt = 0; mt < 2; mt++) { vs[mt][0] = quad_sum(vs[mt][0]); vs[mt][1] = quad_sum(vs[mt][1]); }
    if (q == 0) {
#pragma unroll
        for (int mt = 0; mt < 2; mt++) {
            vbuf[mrow + mt * 16 + g][nhalf] = vs[mt][0];
            vbuf[mrow + mt * 16 + g + 8][nhalf] = vs[mt][1];
        }
    }
    __syncthreads();
#pragma unroll
    for (int mt = 0; mt < 2; mt++) {
        int lr0 = mrow + mt * 16 + g;
        float r0std = rsqrtf((vbuf[lr0][0] + vbuf[lr0][1]) * (1.f / HH) + 1e-5f);
        float r1std = rsqrtf((vbuf[lr0 + 8][0] + vbuf[lr0 + 8][1]) * (1.f / HH) + 1e-5f);
        int gr0 = row0 + lr0, gr1 = gr0 + 8;
#pragma unroll
        for (int j = 0; j < 8; j++) {
            int jc = n0 + 8 * j + 2 * q;
            float2 lw = *(const float2*)&lnw[jc];
            float2 lb = *(const float2*)&lnb[jc];
            float2 o0, o1;
            o0.x = c[mt][j][0] * r0std * lw.x + lb.x;
            o0.y = c[mt][j][1] * r0std * lw.y + lb.y;
            o1.x = c[mt][j][2] * r1std * lw.x + lb.x;
            o1.y = c[mt][j][3] * r1std * lw.y + lb.y;
            *(float2*)&g_h[(size_t)gr0 * HH + jc] = o0;
            *(float2*)&g_h[(size_t)gr1 * HH + jc] = o1;
        }
    }
}

// ---------------- edge MLP: gather-GEMM (K=256) + fused W2 reduction ----------------
__global__ void __launch_bounds__(NTH, 2) k_edgemlp(const int* __restrict__ eli, int Q,
        const float* __restrict__ W1, const float* __restrict__ b1,
        const float* __restrict__ W2, const float* __restrict__ b2,
        float* __restrict__ out) {
    __shared__ uint2 As[2][128][9];
    __shared__ uint2 Ws[2][8][132];
    __shared__ float pbuf[128][2];
    __shared__ int sbase[128], dbase[128];
    GEMM_DECLS
    const int q0 = blockIdx.x * 128;

    if (t < 128) {
        int qq = q0 + t, s = 0, d = 0;
        if (qq < Q) { s = eli[qq]; d = eli[Q + qq]; }
        sbase[t] = s * HH; dbase[t] = d * HH;
    }
    __syncthreads();
    const float* Asrc = &g_h[(size_t)sbase[ar]];
    const float* Adst = &g_h[(size_t)dbase[ar]];

    PREFETCH(Asrc, W1);
    STAGE(0);
    const int NT = 16;
#pragma unroll 2
    for (int it = 0; it < NT; it++) {
        int cur = it & 1;
        __syncthreads();
        if (it + 1 < NT) {
            int nx = it + 1;
            const float* Ap = (nx < 8) ? (Asrc + nx * 16) : (Adst + (nx - 8) * 16);
            PREFETCH(Ap, W1 + (size_t)nx * 16 * HH);
        }
        GEMM_COMPUTE(cur)
        if (it + 1 < NT) STAGE(cur ^ 1);
    }

    float s[2][2];
#pragma unroll
    for (int mt = 0; mt < 2; mt++) { s[mt][0] = 0.f; s[mt][1] = 0.f; }
#pragma unroll
    for (int mt = 0; mt < 2; mt++)
#pragma unroll
        for (int j = 0; j < 8; j++) {
            int jc = n0 + 8 * j + 2 * q;
            float2 bv = *(const float2*)&b1[jc];
            float2 wv = *(const float2*)&W2[jc];
            s[mt][0] = fmaf(fmaxf(c[mt][j][0] + bv.x, 0.f), wv.x, s[mt][0]);
            s[mt][0] = fmaf(fmaxf(c[mt][j][1] + bv.y, 0.f), wv.y, s[mt][0]);
            s[mt][1] = fmaf(fmaxf(c[mt][j][2] + bv.x, 0.f), wv.x, s[mt][1]);
            s[mt][1] = fmaf(fmaxf(c[mt][j][3] + bv.y, 0.f), wv.y, s[mt][1]);
        }
#pragma unroll
    for (int mt = 0; mt < 2; mt++) { s[mt][0] = quad_sum(s[mt][0]); s[mt][1] = quad_sum(s[mt][1]); }
    __syncthreads();
    if (q == 0) {
#pragma unroll
        for (int mt = 0; mt < 2; mt++) {
            pbuf[mrow + mt * 16 + g][nhalf] = s[mt][0];
            pbuf[mrow + mt * 16 + g + 8][nhalf] = s[mt][1];
        }
    }
    __syncthreads();
    if (nhalf == 0 && q == 0) {
        float b2v = b2[0];
#pragma unroll
        for (int mt = 0; mt < 2; mt++) {
            int lr0 = mrow + mt * 16 + g;
            int q0g = q0 + lr0;
            if (q0g < Q)     out[q0g]     = pbuf[lr0][0] + pbuf[lr0][1] + b2v;
            if (q0g + 8 < Q) out[q0g + 8] = pbuf[lr0 + 8][0] + pbuf[lr0 + 8][1] + b2v;
        }
    }
}

// ---------------- host launch ----------------
extern "C" void kernel_launch(void* const* d_in, const int* in_sizes, int n_in,
                              void* d_out, int out_size) {
    const float* x    = (const float*)d_in[0];
    const int*   ei   = (const int*)d_in[1];
    const int*   eli  = (const int*)d_in[2];
    const float* p0Wp = (const float*)d_in[3];
    const float* p0bp = (const float*)d_in[4];
    const float* p0Wl = (const float*)d_in[5];
    const float* p0bl = (const float*)d_in[6];
    const float* p0Wr = (const float*)d_in[7];
    const float* Wp_s = (const float*)d_in[8];
    const float* bp_s = (const float*)d_in[9];
    const float* Wl_s = (const float*)d_in[10];
    const float* bl_s = (const float*)d_in[11];
    const float* Wr_s = (const float*)d_in[12];
    const float* ln_w = (const float*)d_in[13];
    const float* ln_b = (const float*)d_in[14];
    const float* eW1  = (const float*)d_in[15];
    const float* eb1  = (const float*)d_in[16];
    const float* eW2  = (const float*)d_in[17];
    const float* eb2  = (const float*)d_in[18];
    float* out = (float*)d_out;

    const int n = in_sizes[0] / 2;
    const int E = in_sizes[1] / 2;
    const int Q = in_sizes[2] / 2;

    cudaFuncSetAttribute(k_combine, cudaFuncAttributeMaxDynamicSharedMemorySize, DSM_TOTAL);

    void* degp = nullptr;
    cudaGetSymbolAddress(&degp, g_deg);
    cudaMemsetAsync(degp, 0, (size_t)n * sizeof(int));
    k_hist_l0<<<(E + 255) / 256, 256>>>(ei, E, x, p0Wp, p0bp, n);
    const int nb2 = (n + SCAN_B - 1) / SCAN_B;
    k_scan1<<<nb2, SCAN_B>>>(n);
    k_scan2<<<1, 1024>>>(nb2);
    k_scan3<<<(n + 255) / 256, 256>>>(n, E);
    k_scatter<<<(E + 255) / 256, 256>>>(ei, E);

    k_combine0<<<(n * 32 + 255) / 256, 256>>>(n, p0Wl, p0bl, p0Wr, ln_w, ln_b);

    const int gb = (n + 127) / 128;   // 782
    for (int l = 0; l < 2; l++) {
        k_proj<<<gb, NTH>>>(Wp_s + (size_t)l * HH * HH, bp_s + (size_t)l * HH);
        k_combine<<<gb, NTH, DSM_TOTAL>>>(n,
                               Wl_s + (size_t)l * HH * HH, Wr_s + (size_t)l * HH * HH,
                               bl_s + (size_t)l * HH,
                               ln_w + (size_t)(l + 1) * HH, ln_b + (size_t)(l + 1) * HH);
    }
    k_edgemlp<<<(Q + 127) / 128, NTH>>>(eli, Q, eW1, eb1, eW2, eb2, out);
}

// round 17
// speedup vs baseline: 1.5194x; 1.5194x over previous
#include <cuda_runtime.h>
#include <cuda_bf16.h>
#include <cstdint>

#define HH 128
#define NPAD 100096          // = 782*128
#define EMAX 1600000
#define NTH 256
#define SCAN_B 512

// ---------------- scratch ----------------
__device__ float g_xp [NPAD * HH];
__device__ float g_acc[NPAD * HH];     // MEAN-aggregated features
__device__ float g_h  [NPAD * HH];
__device__ float g_xp0[NPAD * 2];
__device__ int   g_deg [NPAD];
__device__ int   g_off [NPAD + 1];
__device__ int   g_cur [NPAD];
__device__ int   g_srcs[EMAX];
__device__ int   g_bsum [4096];
__device__ int   g_bsumx[4096];

__device__ __forceinline__ float warp_sum(float v) {
#pragma unroll
    for (int o = 16; o > 0; o >>= 1) v += __shfl_xor_sync(0xffffffffu, v, o);
    return v;
}
__device__ __forceinline__ float quad_sum(float v) {
    v += __shfl_xor_sync(0xffffffffu, v, 1);
    v += __shfl_xor_sync(0xffffffffu, v, 2);
    return v;
}
// pack two floats' bf16-hi into one u32 (low=a, high=b); lo parts in 'lo'
__device__ __forceinline__ uint32_t pack_hilo(float a, float b, uint32_t& lo) {
    __nv_bfloat16 ha = __float2bfloat16(a), hb = __float2bfloat16(b);
    float ra = a - __bfloat162float(ha), rb = b - __bfloat162float(hb);
    __nv_bfloat16 la = __float2bfloat16(ra), lb = __float2bfloat16(rb);
    lo = (uint32_t)__bfloat16_as_ushort(la) | ((uint32_t)__bfloat16_as_ushort(lb) << 16);
    return (uint32_t)__bfloat16_as_ushort(ha) | ((uint32_t)__bfloat16_as_ushort(hb) << 16);
}

#define MMA_BF16(d, a, b0v, b1v)                                                 \
    asm volatile(                                                                \
        "mma.sync.aligned.m16n8k16.row.col.f32.bf16.bf16.f32 "                   \
        "{%0,%1,%2,%3}, {%4,%5,%6,%7}, {%8,%9}, {%0,%1,%2,%3};"                  \
        : "+f"(d[0]), "+f"(d[1]), "+f"(d[2]), "+f"(d[3])                         \
        : "r"((a)[0]), "r"((a)[1]), "r"((a)[2]), "r"((a)[3]), "r"(b0v), "r"(b1v))

// ================= hist + layer-0 projection, fused =================
__global__ void k_hist_l0(const int* __restrict__ ei, int E,
                          const float* __restrict__ x, const float* __restrict__ Wp,
                          const float* __restrict__ bp, int n) {
    int e = blockIdx.x * blockDim.x + threadIdx.x;
    if (e < n) {
        float x0 = x[2 * e], x1 = x[2 * e + 1];
        g_xp0[2 * e]     = fmaxf(fmaf(x0, Wp[0], fmaf(x1, Wp[2], bp[0])), 0.f);
        g_xp0[2 * e + 1] = fmaxf(fmaf(x0, Wp[1], fmaf(x1, Wp[3], bp[1])), 0.f);
    }
    if (e < E) atomicAdd(&g_deg[ei[E + e]], 1);
}

// ================= CSR scans =================
__global__ void __launch_bounds__(SCAN_B) k_scan1(int n) {
    __shared__ int sm[SCAN_B];
    int t = threadIdx.x;
    int idx = blockIdx.x * SCAN_B + t;
    int v = (idx < n) ? g_deg[idx] : 0;
    sm[t] = v;
    __syncthreads();
#pragma unroll
    for (int off = 1; off < SCAN_B; off <<= 1) {
        int add = (t >= off) ? sm[t - off] : 0;
        __syncthreads();
        sm[t] += add;
        __syncthreads();
    }
    if (idx < n) g_off[idx] = sm[t] - v;
    if (t == SCAN_B - 1) g_bsum[blockIdx.x] = sm[t];
}
__global__ void __launch_bounds__(1024) k_scan2(int nb) {
    __shared__ int sm[1024];
    int t = threadIdx.x;
    int v = (t < nb) ? g_bsum[t] : 0;
    sm[t] = v;
    __syncthreads();
#pragma unroll
    for (int off = 1; off < 1024; off <<= 1) {
        int add = (t >= off) ? sm[t - off] : 0;
        __syncthreads();
        sm[t] += add;
        __syncthreads();
    }
    if (t < nb) g_bsumx[t] = sm[t] - v;
}
__global__ void k_scan3(int n, int E) {
    int idx = blockIdx.x * blockDim.x + threadIdx.x;
    if (idx == 0) g_off[n] = E;
    if (idx >= n) return;
    int o = g_off[idx] + g_bsumx[idx / SCAN_B];
    g_off[idx] = o;
    g_cur[idx] = o;
}
__global__ void k_scatter(const int* __restrict__ ei, int E) {
    int e = blockIdx.x * blockDim.x + threadIdx.x;
    if (e >= E) return;
    int s = ei[e], d = ei[E + e];
    int pos = atomicAdd(&g_cur[d], 1);
    g_srcs[pos] = s;
}

// ============ layer 0 combine: CSR mean-gather (dim2) + combine + LN ============
__global__ void __launch_bounds__(256) k_combine0(int n, const float* __restrict__ Wl,
        const float* __restrict__ bl, const float* __restrict__ Wr,
        const float* __restrict__ lnw, const float* __restrict__ lnb) {
    int node = (blockIdx.x * 256 + threadIdx.x) >> 5;
    int lane = threadIdx.x & 31;
    if (node >= n) return;
    int beg = g_off[node], end = g_off[node + 1];
    float m0 = 0.f, m1 = 0.f;
    for (int j = beg + lane; j < end; j += 32) {
        int s = __ldg(&g_srcs[j]);
        float2 v = *(const float2*)&g_xp0[2 * s];
        m0 += v.x; m1 += v.y;
    }
    m0 = warp_sum(m0); m1 = warp_sum(m1);
    float inv = 1.f / fmaxf((float)(end - beg), 1.f);
    m0 *= inv; m1 *= inv;
    float p0 = g_xp0[2 * node], p1 = g_xp0[2 * node + 1];
    float v[4]; float s = 0.f;
#pragma unroll
    for (int k = 0; k < 4; k++) {
        int c = lane + 32 * k;
        v[k] = fmaf(m0, Wl[c], fmaf(m1, Wl[HH + c],
               fmaf(p0, Wr[c], fmaf(p1, Wr[HH + c], bl[c]))));
        s += v[k];
    }
    s = warp_sum(s);
    float mu = s * (1.f / HH);
    float q = 0.f;
#pragma unroll
    for (int k = 0; k < 4; k++) { v[k] -= mu; q += v[k] * v[k]; }
    q = warp_sum(q);
    float rstd = rsqrtf(q * (1.f / HH) + 1e-5f);
    size_t base = (size_t)node * HH;
#pragma unroll
    for (int k = 0; k < 4; k++) {
        int c = lane + 32 * k;
        g_h[base + c] = v[k] * rstd * lnw[c] + lnb[c];
    }
}

// ================= aggregation: CSR gather-reduce, warp per node =================
__global__ void __launch_bounds__(256) k_gagg(int n) {
    int node = (blockIdx.x * 256 + threadIdx.x) >> 5;
    int lane = threadIdx.x & 31;
    if (node >= n) return;
    int beg = g_off[node], end = g_off[node + 1];
    float4 a0 = make_float4(0.f, 0.f, 0.f, 0.f);
    float4 a1 = make_float4(0.f, 0.f, 0.f, 0.f);
    int j = beg;
    for (; j + 4 <= end; j += 4) {
        int s0 = __ldg(&g_srcs[j]),     s1 = __ldg(&g_srcs[j + 1]);
        int s2 = __ldg(&g_srcs[j + 2]), s3 = __ldg(&g_srcs[j + 3]);
        float4 v0 = *(const float4*)&g_xp[(size_t)s0 * HH + lane * 4];
        float4 v1 = *(const float4*)&g_xp[(size_t)s1 * HH + lane * 4];
        float4 v2 = *(const float4*)&g_xp[(size_t)s2 * HH + lane * 4];
        float4 v3 = *(const float4*)&g_xp[(size_t)s3 * HH + lane * 4];
        a0.x += v0.x + v1.x; a0.y += v0.y + v1.y;
        a0.z += v0.z + v1.z; a0.w += v0.w + v1.w;
        a1.x += v2.x + v3.x; a1.y += v2.y + v3.y;
        a1.z += v2.z + v3.z; a1.w += v2.w + v3.w;
    }
    for (; j < end; j++) {
        int s0 = __ldg(&g_srcs[j]);
        float4 v0 = *(const float4*)&g_xp[(size_t)s0 * HH + lane * 4];
        a0.x += v0.x; a0.y += v0.y; a0.z += v0.z; a0.w += v0.w;
    }
    float inv = 1.f / fmaxf((float)(end - beg), 1.f);
    float4 a;
    a.x = (a0.x + a1.x) * inv; a.y = (a0.y + a1.y) * inv;
    a.z = (a0.z + a1.z) * inv; a.w = (a0.w + a1.w) * inv;
    *(float4*)&g_acc[(size_t)node * HH + lane * 4] = a;
}

// =================== 3xBF16 m16n8k16 MMA GEMM core, 4x2 warp grid (r13) ===================
#define GEMM_DECLS                                                            \
    const int t = threadIdx.x;                                                \
    const int warp = t >> 5, lane = t & 31;                                   \
    const int g = lane >> 2, q = lane & 3;                                    \
    const int mrow = (warp & 3) * 32;                                         \
    const int n0 = (warp >> 2) * 64;                                          \
    const int nhalf = warp >> 2;                                              \
    const int ar = t >> 1, akb = (t & 1) * 8, ac4 = (t & 1) * 4;              \
    const int k2r = t >> 5, nb = (t & 31) * 4;                                \
    float4 pa0, pa1, pw0, pw1;                                                \
    float c[2][8][4];                                                         \
    _Pragma("unroll")                                                         \
    for (int mt = 0; mt < 2; mt++)                                            \
        _Pragma("unroll")                                                     \
        for (int j = 0; j < 8; j++)                                           \
            _Pragma("unroll")                                                 \
            for (int u = 0; u < 4; u++) c[mt][j][u] = 0.f;                    \
    (void)nhalf;

#define STAGE(buf)                                                            \
    {                                                                         \
        uint32_t lo_; uint2 e_;                                               \
        e_.x = pack_hilo(pa0.x, pa0.y, lo_); e_.y = lo_; As[buf][ar][ac4 + 0] = e_; \
        e_.x = pack_hilo(pa0.z, pa0.w, lo_); e_.y = lo_; As[buf][ar][ac4 + 1] = e_; \
        e_.x = pack_hilo(pa1.x, pa1.y, lo_); e_.y = lo_; As[buf][ar][ac4 + 2] = e_; \
        e_.x = pack_hilo(pa1.z, pa1.w, lo_); e_.y = lo_; As[buf][ar][ac4 + 3] = e_; \
        e_.x = pack_hilo(pw0.x, pw1.x, lo_); e_.y = lo_; Ws[buf][k2r][nb + 0] = e_; \
        e_.x = pack_hilo(pw0.y, pw1.y, lo_); e_.y = lo_; Ws[buf][k2r][nb + 1] = e_; \
        e_.x = pack_hilo(pw0.z, pw1.z, lo_); e_.y = lo_; Ws[buf][k2r][nb + 2] = e_; \
        e_.x = pack_hilo(pw0.w, pw1.w, lo_); e_.y = lo_; Ws[buf][k2r][nb + 3] = e_; \
    }

#define PREFETCH(Ap, Wp_)                                                     \
    {                                                                         \
        pa0 = *(const float4*)((Ap) + akb);                                   \
        pa1 = *(const float4*)((Ap) + akb + 4);                               \
        pw0 = *(const float4*)&(Wp_)[(size_t)(2 * k2r) * HH + nb];            \
        pw1 = *(const float4*)&(Wp_)[(size_t)(2 * k2r + 1) * HH + nb];        \
    }

#define GEMM_COMPUTE(cur)                                                     \
    {                                                                         \
        uint32_t ah[2][4], al[2][4];                                          \
        _Pragma("unroll")                                                     \
        for (int mt = 0; mt < 2; mt++) {                                      \
            int r = mrow + mt * 16;                                           \
            uint2 x0 = As[cur][r + g][q];                                     \
            uint2 x1 = As[cur][r + g + 8][q];                                 \
            uint2 x2 = As[cur][r + g][q + 4];                                 \
            uint2 x3 = As[cur][r + g + 8][q + 4];                             \
            ah[mt][0] = x0.x; al[mt][0] = x0.y;                               \
            ah[mt][1] = x1.x; al[mt][1] = x1.y;                               \
            ah[mt][2] = x2.x; al[mt][2] = x2.y;                               \
            ah[mt][3] = x3.x; al[mt][3] = x3.y;                               \
        }                                                                     \
        _Pragma("unroll")                                                     \
        for (int j = 0; j < 8; j++) {                                         \
            int nn = n0 + 8 * j + g;                                          \
            uint2 b0 = Ws[cur][q][nn];                                        \
            uint2 b1 = Ws[cur][q + 4][nn];                                    \
            MMA_BF16(c[0][j], ah[0], b0.y, b1.y);                             \
            MMA_BF16(c[0][j], al[0], b0.x, b1.x);                             \
            MMA_BF16(c[0][j], ah[0], b0.x, b1.x);                             \
            MMA_BF16(c[1][j], ah[1], b0.y, b1.y);                             \
            MMA_BF16(c[1][j], al[1], b0.x, b1.x);                             \
            MMA_BF16(c[1][j], ah[1], b0.x, b1.x);                             \
        }                                                                     \
    }

// ---------------- proj GEMM: xp = relu(h @ Wp + bp), K=128 ----------------
__global__ void __launch_bounds__(NTH, 2) k_proj(const float* __restrict__ W,
                                                 const float* __restrict__ bias) {
    __shared__ uint2 As[2][128][9];
    __shared__ uint2 Ws[2][8][132];
    GEMM_DECLS
    const int row0 = blockIdx.x * 128;
    const float* Arow = &g_h[(size_t)(row0 + ar) * HH];

    PREFETCH(Arow, W);
    STAGE(0);

    const int NT = HH / 16;  // 8
#pragma unroll 2
    for (int it = 0; it < NT; it++) {
        int cur = it & 1;
        __syncthreads();
        if (it + 1 < NT) {
            int k0 = (it + 1) * 16;
            PREFETCH(Arow + k0, W + (size_t)k0 * HH);
        }
        GEMM_COMPUTE(cur)
        if (it + 1 < NT) STAGE(cur ^ 1);
    }

#pragma unroll
    for (int mt = 0; mt < 2; mt++) {
        int r0 = row0 + mrow + mt * 16 + g, r1 = r0 + 8;
#pragma unroll
        for (int j = 0; j < 8; j++) {
            int jc = n0 + 8 * j + 2 * q;
            float2 bv = *(const float2*)&bias[jc];
            float2 o0, o1;
            o0.x = fmaxf(c[mt][j][0] + bv.x, 0.f); o0.y = fmaxf(c[mt][j][1] + bv.y, 0.f);
            o1.x = fmaxf(c[mt][j][2] + bv.x, 0.f); o1.y = fmaxf(c[mt][j][3] + bv.y, 0.f);
            *(float2*)&g_xp[(size_t)r0 * HH + jc] = o0;
            *(float2*)&g_xp[(size_t)r1 * HH + jc] = o1;
        }
    }
}

// ---------------- combine GEMM (K=256: mean | xp) + fused LN ----------------
__global__ void __launch_bounds__(NTH, 2) k_combine(const float* __restrict__ Wl,
        const float* __restrict__ Wr, const float* __restrict__ bl,
        const float* __restrict__ lnw, const float* __restrict__ lnb) {
    __shared__ uint2 As[2][128][9];
    __shared__ uint2 Ws[2][8][132];
    __shared__ float pbuf[128][2];
    __shared__ float vbuf[128][2];
    GEMM_DECLS
    const int row0 = blockIdx.x * 128;
    const float* Aa = &g_acc[(size_t)(row0 + ar) * HH];
    const float* Ax = &g_xp[(size_t)(row0 + ar) * HH];

    PREFETCH(Aa, Wl);
    STAGE(0);

    const int NT = 16;  // K=256 / 16
#pragma unroll 2
    for (int it = 0; it < NT; it++) {
        int cur = it & 1;
        __syncthreads();
        if (it + 1 < NT) {
            int nx = it + 1;
            const float* Ap;
            const float* Wn;
            if (nx < 8) { Ap = Aa + nx * 16; Wn = Wl + (size_t)nx * 16 * HH; }
            else        { Ap = Ax + (nx - 8) * 16; Wn = Wr + (size_t)(nx - 8) * 16 * HH; }
            PREFETCH(Ap, Wn);
        }
        GEMM_COMPUTE(cur)
        if (it + 1 < NT) STAGE(cur ^ 1);
    }

    // bias + per-row partial sums over this warp's 64 cols
    float s[2][2];
#pragma unroll
    for (int mt = 0; mt < 2; mt++) { s[mt][0] = 0.f; s[mt][1] = 0.f; }
#pragma unroll
    for (int mt = 0; mt < 2; mt++)
#pragma unroll
        for (int j = 0; j < 8; j++) {
            int jc = n0 + 8 * j + 2 * q;
            float2 bv = *(const float2*)&bl[jc];
            c[mt][j][0] += bv.x; c[mt][j][1] += bv.y;
            c[mt][j][2] += bv.x; c[mt][j][3] += bv.y;
            s[mt][0] += c[mt][j][0] + c[mt][j][1];
            s[mt][1] += c[mt][j][2] + c[mt][j][3];
        }
#pragma unroll
    for (int mt = 0; mt < 2; mt++) { s[mt][0] = quad_sum(s[mt][0]); s[mt][1] = quad_sum(s[mt][1]); }
    __syncthreads();
    if (q == 0) {
#pragma unroll
        for (int mt = 0; mt < 2; mt++) {
            pbuf[mrow + mt * 16 + g][nhalf] = s[mt][0];
            pbuf[mrow + mt * 16 + g + 8][nhalf] = s[mt][1];
        }
    }
    __syncthreads();
    float mu[2][2], vs[2][2];
#pragma unroll
    for (int mt = 0; mt < 2; mt++) {
        int lr0 = mrow + mt * 16 + g;
        mu[mt][0] = (pbuf[lr0][0] + pbuf[lr0][1]) * (1.f / HH);
        mu[mt][1] = (pbuf[lr0 + 8][0] + pbuf[lr0 + 8][1]) * (1.f / HH);
        vs[mt][0] = 0.f; vs[mt][1] = 0.f;
    }
#pragma unroll
    for (int mt = 0; mt < 2; mt++)
#pragma unroll
        for (int j = 0; j < 8; j++) {
            c[mt][j][0] -= mu[mt][0]; c[mt][j][1] -= mu[mt][0];
            c[mt][j][2] -= mu[mt][1]; c[mt][j][3] -= mu[mt][1];
            vs[mt][0] += c[mt][j][0] * c[mt][j][0] + c[mt][j][1] * c[mt][j][1];
            vs[mt][1] += c[mt][j][2] * c[mt][j][2] + c[mt][j][3] * c[mt][j][3];
        }
#pragma unroll
    for (int mt = 0; mt < 2; mt++) { vs[mt][0] = quad_sum(vs[mt][0]); vs[mt][1] = quad_sum(vs[mt][1]); }
    if (q == 0) {
#pragma unroll
        for (int mt = 0; mt < 2; mt++) {
            vbuf[mrow + mt * 16 + g][nhalf] = vs[mt][0];
            vbuf[mrow + mt * 16 + g + 8][nhalf] = vs[mt][1];
        }
    }
    __syncthreads();
#pragma unroll
    for (int mt = 0; mt < 2; mt++) {
        int lr0 = mrow + mt * 16 + g;
        float r0std = rsqrtf((vbuf[lr0][0] + vbuf[lr0][1]) * (1.f / HH) + 1e-5f);
        float r1std = rsqrtf((vbuf[lr0 + 8][0] + vbuf[lr0 + 8][1]) * (1.f / HH) + 1e-5f);
        int gr0 = row0 + lr0, gr1 = gr0 + 8;
#pragma unroll
        for (int j = 0; j < 8; j++) {
            int jc = n0 + 8 * j + 2 * q;
            float2 lw = *(const float2*)&lnw[jc];
            float2 lb = *(const float2*)&lnb[jc];
            float2 o0, o1;
            o0.x = c[mt][j][0] * r0std * lw.x + lb.x;
            o0.y = c[mt][j][1] * r0std * lw.y + lb.y;
            o1.x = c[mt][j][2] * r1std * lw.x + lb.x;
            o1.y = c[mt][j][3] * r1std * lw.y + lb.y;
            *(float2*)&g_h[(size_t)gr0 * HH + jc] = o0;
            *(float2*)&g_h[(size_t)gr1 * HH + jc] = o1;
        }
    }
}

// ---------------- edge MLP: gather-GEMM (K=256) + fused W2 reduction ----------------
__global__ void __launch_bounds__(NTH, 2) k_edgemlp(const int* __restrict__ eli, int Q,
        const float* __restrict__ W1, const float* __restrict__ b1,
        const float* __restrict__ W2, const float* __restrict__ b2,
        float* __restrict__ out) {
    __shared__ uint2 As[2][128][9];
    __shared__ uint2 Ws[2][8][132];
    __shared__ float pbuf[128][2];
    __shared__ int sbase[128], dbase[128];
    GEMM_DECLS
    const int q0 = blockIdx.x * 128;

    if (t < 128) {
        int qq = q0 + t, s = 0, d = 0;
        if (qq < Q) { s = eli[qq]; d = eli[Q + qq]; }
        sbase[t] = s * HH; dbase[t] = d * HH;
    }
    __syncthreads();
    const float* Asrc = &g_h[(size_t)sbase[ar]];
    const float* Adst = &g_h[(size_t)dbase[ar]];

    PREFETCH(Asrc, W1);
    STAGE(0);

    const int NT = 16;
#pragma unroll 2
    for (int it = 0; it < NT; it++) {
        int cur = it & 1;
        __syncthreads();
        if (it + 1 < NT) {
            int nx = it + 1;
            const float* Ap = (nx < 8) ? (Asrc + nx * 16) : (Adst + (nx - 8) * 16);
            PREFETCH(Ap, W1 + (size_t)nx * 16 * HH);
        }
        GEMM_COMPUTE(cur)
        if (it + 1 < NT) STAGE(cur ^ 1);
    }

    float s[2][2];
#pragma unroll
    for (int mt = 0; mt < 2; mt++) { s[mt][0] = 0.f; s[mt][1] = 0.f; }
#pragma unroll
    for (int mt = 0; mt < 2; mt++)
#pragma unroll
        for (int j = 0; j < 8; j++) {
            int jc = n0 + 8 * j + 2 * q;
            float2 bv = *(const float2*)&b1[jc];
            float2 wv = *(const float2*)&W2[jc];
            s[mt][0] = fmaf(fmaxf(c[mt][j][0] + bv.x, 0.f), wv.x, s[mt][0]);
            s[mt][0] = fmaf(fmaxf(c[mt][j][1] + bv.y, 0.f), wv.y, s[mt][0]);
            s[mt][1] = fmaf(fmaxf(c[mt][j][2] + bv.x, 0.f), wv.x, s[mt][1]);
            s[mt][1] = fmaf(fmaxf(c[mt][j][3] + bv.y, 0.f), wv.y, s[mt][1]);
        }
#pragma unroll
    for (int mt = 0; mt < 2; mt++) { s[mt][0] = quad_sum(s[mt][0]); s[mt][1] = quad_sum(s[mt][1]); }
    __syncthreads();
    if (q == 0) {
#pragma unroll
        for (int mt = 0; mt < 2; mt++) {
            pbuf[mrow + mt * 16 + g][nhalf] = s[mt][0];
            pbuf[mrow + mt * 16 + g + 8][nhalf] = s[mt][1];
        }
    }
    __syncthreads();
    if (nhalf == 0 && q == 0) {
        float b2v = b2[0];
#pragma unroll
        for (int mt = 0; mt < 2; mt++) {
            int lr0 = mrow + mt * 16 + g;
            int q0g = q0 + lr0;
            if (q0g < Q)     out[q0g]     = pbuf[lr0][0] + pbuf[lr0][1] + b2v;
            if (q0g + 8 < Q) out[q0g + 8] = pbuf[lr0 + 8][0] + pbuf[lr0 + 8][1] + b2v;
        }
    }
}

// ---------------- host launch ----------------
extern "C" void kernel_launch(void* const* d_in, const int* in_sizes, int n_in,
                              void* d_out, int out_size) {
    const float* x    = (const float*)d_in[0];
    const int*   ei   = (const int*)d_in[1];
    const int*   eli  = (const int*)d_in[2];
    const float* p0Wp = (const float*)d_in[3];
    const float* p0bp = (const float*)d_in[4];
    const float* p0Wl = (const float*)d_in[5];
    const float* p0bl = (const float*)d_in[6];
    const float* p0Wr = (const float*)d_in[7];
    const float* Wp_s = (const float*)d_in[8];
    const float* bp_s = (const float*)d_in[9];
    const float* Wl_s = (const float*)d_in[10];
    const float* bl_s = (const float*)d_in[11];
    const float* Wr_s = (const float*)d_in[12];
    const float* ln_w = (const float*)d_in[13];
    const float* ln_b = (const float*)d_in[14];
    const float* eW1  = (const float*)d_in[15];
    const float* eb1  = (const float*)d_in[16];
    const float* eW2  = (const float*)d_in[17];
    const float* eb2  = (const float*)d_in[18];
    float* out = (float*)d_out;

    const int n = in_sizes[0] / 2;
    const int E = in_sizes[1] / 2;
    const int Q = in_sizes[2] / 2;

    // ---- CSR build (once) + fused layer-0 projection ----
    void* degp = nullptr;
    cudaGetSymbolAddress(&degp, g_deg);
    cudaMemsetAsync(degp, 0, (size_t)n * sizeof(int));
    k_hist_l0<<<(E + 255) / 256, 256>>>(ei, E, x, p0Wp, p0bp, n);
    const int nb2 = (n + SCAN_B - 1) / SCAN_B;
    k_scan1<<<nb2, SCAN_B>>>(n);
    k_scan2<<<1, 1024>>>(nb2);
    k_scan3<<<(n + 255) / 256, 256>>>(n, E);
    k_scatter<<<(E + 255) / 256, 256>>>(ei, E);

    k_combine0<<<(n * 32 + 255) / 256, 256>>>(n, p0Wl, p0bl, p0Wr, ln_w, ln_b);

    // ---- layers 1..2 ----
    const int gb = (n + 127) / 128;   // 782
    const int gaggB = (n * 32 + 255) / 256;
    for (int l = 0; l < 2; l++) {
        k_proj<<<gb, NTH>>>(Wp_s + (size_t)l * HH * HH, bp_s + (size_t)l * HH);
        k_gagg<<<gaggB, 256>>>(n);
        k_combine<<<gb, NTH>>>(Wl_s + (size_t)l * HH * HH, Wr_s + (size_t)l * HH * HH,
                               bl_s + (size_t)l * HH,
                               ln_w + (size_t)(l + 1) * HH, ln_b + (size_t)(l + 1) * HH);
    }
    k_edgemlp<<<(Q + 127) / 128, NTH>>>(eli, Q, eW1, eb1, eW2, eb2, out);
}